// round 6
// baseline (speedup 1.0000x reference)
#include <cuda_runtime.h>
#include <cstdint>

#define NMAX (1 << 20)
#define L1B  4096      // smem ladder level (one block, records in shared)
#define L2B  65536
#define L3B  262144    // top cache boundary

// Walk record, 32B/node: [2i]=(chp, shp, cth, sth) half-angle cos/sin,
//                        [2i+1]=(d, next_as_int_bits, 0, 0)
__device__ float4 g_W[2 * NMAX];        // 32MB
// Global transform cache: [2i]=(qw,qx,qy,qz) quat, [2i+1]=(tx,ty,tz,0). 8MB
__device__ float4 g_Gq[2 * L3B];
__device__ float4 g_coords[NMAX];       // 16MB
__device__ double g_acc;
__device__ unsigned g_done;

// ---------------------------------------------------------------------------
// Exact full-angle recovery from half-angle sincos.
__device__ __forceinline__ void full_from_half(float ch, float sh,
                                               float& c, float& s) {
    c = fmaf(-2.f * sh, sh, 1.f);
    s = 2.f * sh * ch;
}

// v' = Rz(phi)*Ry(theta) * v given full-angle (cp,sp,ct,st).
__device__ __forceinline__ void rot_apply(float cp, float sp, float ct, float st,
                                          float vx, float vy, float vz,
                                          float& ox, float& oy, float& oz) {
    float u = fmaf(ct, vx, st * vz);
    oz = fmaf(ct, vz, -st * vx);
    ox = fmaf(cp, u, -sp * vy);
    oy = fmaf(sp, u, cp * vy);
}

__device__ __forceinline__ void qmul(float w1, float x1, float y1, float z1,
                                     float w2, float x2, float y2, float z2,
                                     float& w, float& x, float& y, float& z) {
    w = w1 * w2 - x1 * x2 - y1 * y2 - z1 * z2;
    x = w1 * x2 + x1 * w2 + y1 * z2 - z1 * y2;
    y = w1 * y2 - x1 * z2 + y1 * w2 + z1 * x2;
    z = w1 * z2 + x1 * y2 - y1 * x2 + z1 * w2;
}

__device__ __forceinline__ void qrot(float w, float x, float y, float z,
                                     float vx, float vy, float vz,
                                     float& ox, float& oy, float& oz) {
    float tx = y * vz - z * vy + w * vx;
    float ty = z * vx - x * vz + w * vy;
    float tz = x * vy - y * vx + w * vz;
    ox = fmaf(2.f, y * tz - z * ty, vx);
    oy = fmaf(2.f, z * tx - x * tz, vy);
    oz = fmaf(2.f, x * ty - y * tx, vz);
}

// ---------------------------------------------------------------------------
// Build walk records. Per-row iota shortcut: if mask_idx[i]==i the masked row
// applies to node i directly; any row where mask_idx[j]!=j is repaired by
// k_scatter afterwards (exact for arbitrary masks, zero-write for iota).
__global__ void k_local(const float* __restrict__ full,
                        const float* __restrict__ masked,
                        const int* __restrict__ mask_idx,
                        const int* __restrict__ parent, int n, int k) {
    int i = blockIdx.x * blockDim.x + threadIdx.x;
    if (i >= n) return;
    const float* row = full + (size_t)i * 9;
    if (i < k && mask_idx[i] == i) row = masked + (size_t)i * 9;
    float phi = row[0], theta = row[1], d = row[2];
    float shp, chp, sth, cth;
    sincosf(0.5f * phi, &shp, &chp);
    sincosf(0.5f * theta, &sth, &cth);
    g_W[2 * i]     = make_float4(chp, shp, cth, sth);
    g_W[2 * i + 1] = make_float4(d, __int_as_float(parent[i]), 0.f, 0.f);
}

__global__ void k_scatter(const float* __restrict__ masked,
                          const int* __restrict__ mask_idx,
                          const int* __restrict__ parent, int k) {
    for (int j = blockIdx.x * blockDim.x + threadIdx.x; j < k;
         j += gridDim.x * blockDim.x) {
        int tgt = mask_idx[j];
        if (tgt == j) continue;
        const float* row = masked + (size_t)j * 9;
        float phi = row[0], theta = row[1], d = row[2];
        float shp, chp, sth, cth;
        sincosf(0.5f * phi, &shp, &chp);
        sincosf(0.5f * theta, &sth, &cth);
        g_W[2 * tgt]     = make_float4(chp, shp, cth, sth);
        g_W[2 * tgt + 1] = make_float4(d, __int_as_float(parent[tgt]), 0.f, 0.f);
    }
}

// ---------------------------------------------------------------------------
// Level 1: single block; stage records for nodes < count into smem (32B each),
// then walk chains to the root entirely in shared memory.
__global__ void k_glob1(int count) {
    extern __shared__ float4 sW[];  // 2 float4 per node
    int tid = threadIdx.x;
    for (int j = tid; j < 2 * count; j += blockDim.x) sW[j] = g_W[j];
    __syncthreads();
    for (int i = tid; i < count; i += blockDim.x) {
        if (i == 0) {
            g_Gq[0] = make_float4(1.f, 0.f, 0.f, 0.f);
            g_Gq[1] = make_float4(0.f, 0.f, 0.f, 0.f);
            g_coords[0] = make_float4(0.f, 0.f, 0.f, 0.f);
            continue;
        }
        float4 h = sW[2 * i];
        float4 e = sW[2 * i + 1];
        float qw = h.x * h.z, qx = -h.y * h.w, qy = h.x * h.w, qz = h.y * h.z;
        float cp, sp, ct, st;
        full_from_half(h.x, h.y, cp, sp);
        full_from_half(h.z, h.w, ct, st);
        float tx = e.x * cp * ct, ty = e.x * sp * ct, tz = -e.x * st;
        int a = __float_as_int(e.y);
        while (a > 0) {
            float4 ah = sW[2 * a];
            float4 ae = sW[2 * a + 1];
            int an = __float_as_int(ae.y);
            float acp, asp, act, ast;
            full_from_half(ah.x, ah.y, acp, asp);
            full_from_half(ah.z, ah.w, act, ast);
            float wx = tx + ae.x;
            rot_apply(acp, asp, act, ast, wx, ty, tz, tx, ty, tz);
            float aqw = ah.x * ah.z, aqx = -ah.y * ah.w,
                  aqy = ah.x * ah.w, aqz = ah.y * ah.z;
            float nw, nx, ny, nz;
            qmul(aqw, aqx, aqy, aqz, qw, qx, qy, qz, nw, nx, ny, nz);
            qw = nw; qx = nx; qy = ny; qz = nz;
            a = an;
        }
        g_Gq[2 * i]     = make_float4(qw, qx, qy, qz);
        g_Gq[2 * i + 1] = make_float4(tx, ty, tz, 0.f);
        g_coords[i] = make_float4(tx, ty, tz, 0.f);
    }
}

// Generic ladder level: walk until index < stop, then compose with cached Gq.
__global__ void k_globN(int start, int end, int stop) {
    int i = start + blockIdx.x * blockDim.x + threadIdx.x;
    if (i >= end) return;
    float4 h = g_W[2 * i];
    float4 e = g_W[2 * i + 1];
    float qw = h.x * h.z, qx = -h.y * h.w, qy = h.x * h.w, qz = h.y * h.z;
    float cp, sp, ct, st;
    full_from_half(h.x, h.y, cp, sp);
    full_from_half(h.z, h.w, ct, st);
    float tx = e.x * cp * ct, ty = e.x * sp * ct, tz = -e.x * st;
    int a = __float_as_int(e.y);
    while (a >= stop) {
        float4 ah = g_W[2 * a];
        float4 ae = g_W[2 * a + 1];
        int an = __float_as_int(ae.y);
        float acp, asp, act, ast;
        full_from_half(ah.x, ah.y, acp, asp);
        full_from_half(ah.z, ah.w, act, ast);
        float wx = tx + ae.x;
        rot_apply(acp, asp, act, ast, wx, ty, tz, tx, ty, tz);
        float aqw = ah.x * ah.z, aqx = -ah.y * ah.w,
              aqy = ah.x * ah.w, aqz = ah.y * ah.z;
        float nw, nx, ny, nz;
        qmul(aqw, aqx, aqy, aqz, qw, qx, qy, qz, nw, nx, ny, nz);
        qw = nw; qx = nx; qy = ny; qz = nz;
        a = an;
    }
    // G = Gq[a] ∘ A  (Gq[0] is identity, no branch needed)
    float4 gq = g_Gq[2 * a];
    float4 gt = g_Gq[2 * a + 1];
    float nw, nx, ny, nz;
    qmul(gq.x, gq.y, gq.z, gq.w, qw, qx, qy, qz, nw, nx, ny, nz);
    float rx, ry, rz;
    qrot(gq.x, gq.y, gq.z, gq.w, tx, ty, tz, rx, ry, rz);
    tx = gt.x + rx; ty = gt.y + ry; tz = gt.z + rz;
    g_Gq[2 * i]     = make_float4(nw, nx, ny, nz);
    g_Gq[2 * i + 1] = make_float4(tx, ty, tz, 0.f);
    g_coords[i] = make_float4(tx, ty, tz, 0.f);
}

// ---------------------------------------------------------------------------
// Main walk (i >= L3B): translation-only hops, then one cached-quat apply.
__global__ void k_coords(int n) {
    int i = L3B + blockIdx.x * blockDim.x + threadIdx.x;
    if (i >= n) return;
    float4 h = g_W[2 * i];
    float4 e = g_W[2 * i + 1];
    float cp, sp, ct, st;
    full_from_half(h.x, h.y, cp, sp);
    full_from_half(h.z, h.w, ct, st);
    float vx = e.x * cp * ct, vy = e.x * sp * ct, vz = -e.x * st;
    int a = __float_as_int(e.y);
    while (a >= L3B) {
        float4 bh = g_W[2 * a];
        float4 be = g_W[2 * a + 1];
        int an = __float_as_int(be.y);
        float bcp, bsp, bct, bst;
        full_from_half(bh.x, bh.y, bcp, bsp);
        full_from_half(bh.z, bh.w, bct, bst);
        float wx = vx + be.x;
        rot_apply(bcp, bsp, bct, bst, wx, vy, vz, vx, vy, vz);
        a = an;
    }
    float4 gq = g_Gq[2 * a];
    float4 gt = g_Gq[2 * a + 1];
    float rx, ry, rz;
    qrot(gq.x, gq.y, gq.z, gq.w, vx, vy, vz, rx, ry, rz);
    g_coords[i] = make_float4(gt.x + rx, gt.y + ry, gt.z + rz, 0.f);
}

// ---------------------------------------------------------------------------
__device__ __forceinline__ float3 f3sub(float4 a, float4 b) {
    return make_float3(a.x - b.x, a.y - b.y, a.z - b.z);
}
__device__ __forceinline__ float3 f3cross(float3 a, float3 b) {
    return make_float3(a.y * b.z - a.z * b.y,
                       a.z * b.x - a.x * b.z,
                       a.x * b.y - a.y * b.x);
}
__device__ __forceinline__ float f3dot(float3 a, float3 b) {
    return fmaf(a.x, b.x, fmaf(a.y, b.y, a.z * b.z));
}

__global__ void k_energy(const int* __restrict__ torsion_atoms,
                         const float* __restrict__ k_tor,
                         const float* __restrict__ n_per,
                         const float* __restrict__ delta,
                         int m, float* __restrict__ out) {
    int t = blockIdx.x * blockDim.x + threadIdx.x;
    float e = 0.0f;
    if (t < m) {
        int4 ta = reinterpret_cast<const int4*>(torsion_atoms)[t];
        float4 p1 = g_coords[ta.x];
        float4 p2 = g_coords[ta.y];
        float4 p3 = g_coords[ta.z];
        float4 p4 = g_coords[ta.w];
        float3 b1 = f3sub(p2, p1);
        float3 b2 = f3sub(p3, p2);
        float3 b3 = f3sub(p4, p3);
        float3 n1 = f3cross(b1, b2);
        float3 n2 = f3cross(b2, b3);
        float inv = 1.0f / (sqrtf(f3dot(b2, b2)) + 1e-8f);
        float3 b2n = make_float3(b2.x * inv, b2.y * inv, b2.z * inv);
        float y = f3dot(f3cross(n1, n2), b2n);
        float x = f3dot(n1, n2);
        float chi = atan2f(y, x);
        e = k_tor[t] * (1.0f + cosf(fmaf(n_per[t], chi, -delta[t])));
    }
    #pragma unroll
    for (int o = 16; o > 0; o >>= 1)
        e += __shfl_down_sync(0xffffffffu, e, o);
    __shared__ float s_warp[8];
    int lane = threadIdx.x & 31;
    int wrp = threadIdx.x >> 5;
    if (lane == 0) s_warp[wrp] = e;
    __syncthreads();
    if (wrp == 0) {
        float v = (lane < (blockDim.x >> 5)) ? s_warp[lane] : 0.0f;
        #pragma unroll
        for (int o = 4; o > 0; o >>= 1)
            v += __shfl_down_sync(0xffffffffu, v, o);
        if (lane == 0) {
            atomicAdd(&g_acc, (double)v);
            __threadfence();
            unsigned done = atomicInc(&g_done, 0xffffffffu);
            if (done == gridDim.x - 1) {
                double total = atomicAdd(&g_acc, 0.0);
                out[0] = (float)total;
                g_acc = 0.0;
                g_done = 0;
            }
        }
    }
}

// ---------------------------------------------------------------------------
extern "C" void kernel_launch(void* const* d_in, const int* in_sizes, int n_in,
                              void* d_out, int out_size) {
    const float* masked_dofs = (const float*)d_in[0];
    const float* full_dofs   = (const float*)d_in[1];
    const float* k_tor       = (const float*)d_in[2];
    const float* n_per       = (const float*)d_in[3];
    const float* delta       = (const float*)d_in[4];
    const int*   mask_idx    = (const int*)d_in[5];
    const int*   parent      = (const int*)d_in[6];
    const int*   tors        = (const int*)d_in[7];

    int K = in_sizes[0] / 9;
    int N = in_sizes[1] / 9;
    int M = in_sizes[2];

    int b1 = (N < L1B) ? N : L1B;
    int b2 = (N < L2B) ? N : L2B;
    int b3 = (N < L3B) ? N : L3B;

    static bool attr_set = false;
    if (!attr_set) {
        cudaFuncSetAttribute(k_glob1, cudaFuncAttributeMaxDynamicSharedMemorySize,
                             2 * L1B * (int)sizeof(float4));
        attr_set = true;
    }

    const int TB = 256;
    k_local<<<(N + TB - 1) / TB, TB>>>(full_dofs, masked_dofs, mask_idx, parent,
                                       N, K);
    k_scatter<<<256, TB>>>(masked_dofs, mask_idx, parent, K);
    k_glob1<<<1, 1024, 2 * b1 * (int)sizeof(float4)>>>(b1);
    if (b2 > b1)
        k_globN<<<(b2 - b1 + TB - 1) / TB, TB>>>(b1, b2, b1);
    if (b3 > b2)
        k_globN<<<(b3 - b2 + TB - 1) / TB, TB>>>(b2, b3, b2);
    if (N > b3)
        k_coords<<<(N - b3 + TB - 1) / TB, TB>>>(N);
    k_energy<<<(M + TB - 1) / TB, TB>>>(tors, k_tor, n_per, delta, M,
                                        (float*)d_out);
}

// round 7
// speedup vs baseline: 1.1389x; 1.1389x over previous
#include <cuda_runtime.h>
#include <cstdint>

#define NMAX (1 << 20)
#define L0B  512       // rung 0: walk to root
#define L1B  4096      // rung 1
#define L2B  65536     // rung 2
#define L3B  262144    // top cache boundary

// Scratch (static device globals).
__device__ float4 g_cs[NMAX];      // (cos phi, sin phi, cos theta, sin theta) 16MB
__device__ float2 g_dp[NMAX];      // (d, parent_as_int_bits)                   8MB
__device__ float4 g_G[3 * L3B];    // full global transforms for nodes < L3B   12MB
__device__ float4 g_coords[NMAX];  // global coordinates                       16MB
__device__ double g_acc;
__device__ unsigned g_done;

// Apply rotation R(phi,theta) from compact form: q = (cp, sp, ct, st).
#define ROT(q, ivx, ivy, ivz, ox, oy, oz)             \
    {                                                 \
        float _u = fmaf((q).z, (ivx), (q).w * (ivz)); \
        (oz) = fmaf((q).z, (ivz), -(q).w * (ivx));    \
        (ox) = fmaf((q).x, _u, -(q).y * (ivy));       \
        (oy) = fmaf((q).y, _u, (q).x * (ivy));        \
    }

// ---------------------------------------------------------------------------
// Build compact params. Per-row iota shortcut: if mask_idx[i]==i use the
// masked row for node i; rows where mask_idx[j]!=j are repaired by k_scatter
// (exact for arbitrary masks, zero writes for the iota case).
__global__ void k_local(const float* __restrict__ full,
                        const float* __restrict__ masked,
                        const int* __restrict__ mask_idx,
                        const int* __restrict__ parent, int n, int k) {
    int i = blockIdx.x * blockDim.x + threadIdx.x;
    if (i >= n) return;
    const float* row = full + (size_t)i * 9;
    if (i < k && mask_idx[i] == i) row = masked + (size_t)i * 9;
    float phi = row[0], theta = row[1], d = row[2];
    float sp, cp, st, ct;
    sincosf(phi, &sp, &cp);
    sincosf(theta, &st, &ct);
    g_cs[i] = make_float4(cp, sp, ct, st);
    g_dp[i] = make_float2(d, __int_as_float(parent[i]));
}

__global__ void k_scatter(const float* __restrict__ masked,
                          const int* __restrict__ mask_idx,
                          const int* __restrict__ parent, int k) {
    for (int j = blockIdx.x * blockDim.x + threadIdx.x; j < k;
         j += gridDim.x * blockDim.x) {
        int tgt = mask_idx[j];
        if (tgt == j) continue;
        const float* row = masked + (size_t)j * 9;
        float phi = row[0], theta = row[1], d = row[2];
        float sp, cp, st, ct;
        sincosf(phi, &sp, &cp);
        sincosf(theta, &st, &ct);
        g_cs[tgt] = make_float4(cp, sp, ct, st);
        g_dp[tgt] = make_float2(d, __int_as_float(parent[tgt]));
    }
}

// ---------------------------------------------------------------------------
// Ladder level: for i in [start, end), compose the full 3x4 global transform,
// walking parents until index < stop, then composing with the cached global.
// Node 0 is identity (reference sets T[0]=eye), handled by stop>=1 + a>0 test.
__global__ void k_glob(int start, int end, int stop) {
    int i = start + blockIdx.x * blockDim.x + threadIdx.x;
    if (i >= end) return;
    if (i == 0) {
        g_G[0] = make_float4(1.f, 0.f, 0.f, 0.f);
        g_G[1] = make_float4(0.f, 1.f, 0.f, 0.f);
        g_G[2] = make_float4(0.f, 0.f, 1.f, 0.f);
        g_coords[0] = make_float4(0.f, 0.f, 0.f, 0.f);
        return;
    }
    float4 cs = g_cs[i];
    float2 dp = g_dp[i];
    float d = dp.x;
    float4 r0 = make_float4(cs.x * cs.z, -cs.y, cs.x * cs.w, d * cs.x * cs.z);
    float4 r1 = make_float4(cs.y * cs.z, cs.x, cs.y * cs.w, d * cs.y * cs.z);
    float4 r2 = make_float4(-cs.w, 0.f, cs.z, -d * cs.w);
    int a = __float_as_int(dp.y);
    while (a >= stop) {
        float4 q = g_cs[a];
        float2 adp = g_dp[a];
        int an = __float_as_int(adp.y);
        float n0x, n1x, n2x, n0y, n1y, n2y, n0z, n1z, n2z, n0w, n1w, n2w;
        ROT(q, r0.x, r1.x, r2.x, n0x, n1x, n2x);
        ROT(q, r0.y, r1.y, r2.y, n0y, n1y, n2y);
        ROT(q, r0.z, r1.z, r2.z, n0z, n1z, n2z);
        float w = r0.w + adp.x;
        ROT(q, w, r1.w, r2.w, n0w, n1w, n2w);
        r0 = make_float4(n0x, n0y, n0z, n0w);
        r1 = make_float4(n1x, n1y, n1z, n1w);
        r2 = make_float4(n2x, n2y, n2z, n2w);
        a = an;
    }
    if (a > 0) {
        float4 G0 = g_G[3 * a + 0];
        float4 G1 = g_G[3 * a + 1];
        float4 G2 = g_G[3 * a + 2];
        float4 n0, n1, n2;
        n0.x = fmaf(G0.x, r0.x, fmaf(G0.y, r1.x, G0.z * r2.x));
        n0.y = fmaf(G0.x, r0.y, fmaf(G0.y, r1.y, G0.z * r2.y));
        n0.z = fmaf(G0.x, r0.z, fmaf(G0.y, r1.z, G0.z * r2.z));
        n0.w = fmaf(G0.x, r0.w, fmaf(G0.y, r1.w, fmaf(G0.z, r2.w, G0.w)));
        n1.x = fmaf(G1.x, r0.x, fmaf(G1.y, r1.x, G1.z * r2.x));
        n1.y = fmaf(G1.x, r0.y, fmaf(G1.y, r1.y, G1.z * r2.y));
        n1.z = fmaf(G1.x, r0.z, fmaf(G1.y, r1.z, G1.z * r2.z));
        n1.w = fmaf(G1.x, r0.w, fmaf(G1.y, r1.w, fmaf(G1.z, r2.w, G1.w)));
        n2.x = fmaf(G2.x, r0.x, fmaf(G2.y, r1.x, G2.z * r2.x));
        n2.y = fmaf(G2.x, r0.y, fmaf(G2.y, r1.y, G2.z * r2.y));
        n2.z = fmaf(G2.x, r0.z, fmaf(G2.y, r1.z, G2.z * r2.z));
        n2.w = fmaf(G2.x, r0.w, fmaf(G2.y, r1.w, fmaf(G2.z, r2.w, G2.w)));
        r0 = n0; r1 = n1; r2 = n2;
    }
    g_G[3 * i + 0] = r0;
    g_G[3 * i + 1] = r1;
    g_G[3 * i + 2] = r2;
    g_coords[i] = make_float4(r0.w, r1.w, r2.w, 0.f);
}

// ---------------------------------------------------------------------------
// Main walk (i >= L3B): translation-only hops until below L3B, then one
// affine apply of the cached global transform.
__global__ void k_coords(int n) {
    int i = L3B + blockIdx.x * blockDim.x + threadIdx.x;
    if (i >= n) return;
    float4 cs = g_cs[i];
    float2 dp = g_dp[i];
    float d = dp.x;
    float vx, vy, vz;
    ROT(cs, d, 0.f, 0.f, vx, vy, vz);
    int a = __float_as_int(dp.y);
    while (a >= L3B) {
        float4 q = g_cs[a];
        float2 adp = g_dp[a];
        int an = __float_as_int(adp.y);
        float w = vx + adp.x, nx, ny, nz;
        ROT(q, w, vy, vz, nx, ny, nz);
        vx = nx; vy = ny; vz = nz;
        a = an;
    }
    if (a > 0) {
        float4 G0 = g_G[3 * a + 0];
        float4 G1 = g_G[3 * a + 1];
        float4 G2 = g_G[3 * a + 2];
        float cx = fmaf(G0.x, vx, fmaf(G0.y, vy, fmaf(G0.z, vz, G0.w)));
        float cy = fmaf(G1.x, vx, fmaf(G1.y, vy, fmaf(G1.z, vz, G1.w)));
        float cz = fmaf(G2.x, vx, fmaf(G2.y, vy, fmaf(G2.z, vz, G2.w)));
        vx = cx; vy = cy; vz = cz;
    }
    g_coords[i] = make_float4(vx, vy, vz, 0.f);
}

// ---------------------------------------------------------------------------
__device__ __forceinline__ float3 f3sub(float4 a, float4 b) {
    return make_float3(a.x - b.x, a.y - b.y, a.z - b.z);
}
__device__ __forceinline__ float3 f3cross(float3 a, float3 b) {
    return make_float3(a.y * b.z - a.z * b.y,
                       a.z * b.x - a.x * b.z,
                       a.x * b.y - a.y * b.x);
}
__device__ __forceinline__ float f3dot(float3 a, float3 b) {
    return fmaf(a.x, b.x, fmaf(a.y, b.y, a.z * b.z));
}

__global__ void k_energy(const int* __restrict__ torsion_atoms,
                         const float* __restrict__ k_tor,
                         const float* __restrict__ n_per,
                         const float* __restrict__ delta,
                         int m, float* __restrict__ out) {
    int t = blockIdx.x * blockDim.x + threadIdx.x;
    float e = 0.0f;
    if (t < m) {
        int4 ta = reinterpret_cast<const int4*>(torsion_atoms)[t];
        float4 p1 = g_coords[ta.x];
        float4 p2 = g_coords[ta.y];
        float4 p3 = g_coords[ta.z];
        float4 p4 = g_coords[ta.w];
        float3 b1 = f3sub(p2, p1);
        float3 b2 = f3sub(p3, p2);
        float3 b3 = f3sub(p4, p3);
        float3 n1 = f3cross(b1, b2);
        float3 n2 = f3cross(b2, b3);
        float inv = 1.0f / (sqrtf(f3dot(b2, b2)) + 1e-8f);
        float3 b2n = make_float3(b2.x * inv, b2.y * inv, b2.z * inv);
        float y = f3dot(f3cross(n1, n2), b2n);
        float x = f3dot(n1, n2);
        float chi = atan2f(y, x);
        e = k_tor[t] * (1.0f + cosf(fmaf(n_per[t], chi, -delta[t])));
    }
    #pragma unroll
    for (int o = 16; o > 0; o >>= 1)
        e += __shfl_down_sync(0xffffffffu, e, o);
    __shared__ float s_warp[8];
    int lane = threadIdx.x & 31;
    int wrp = threadIdx.x >> 5;
    if (lane == 0) s_warp[wrp] = e;
    __syncthreads();
    if (wrp == 0) {
        float v = (lane < (blockDim.x >> 5)) ? s_warp[lane] : 0.0f;
        #pragma unroll
        for (int o = 4; o > 0; o >>= 1)
            v += __shfl_down_sync(0xffffffffu, v, o);
        if (lane == 0) {
            atomicAdd(&g_acc, (double)v);
            __threadfence();
            unsigned done = atomicInc(&g_done, 0xffffffffu);
            if (done == gridDim.x - 1) {
                double total = atomicAdd(&g_acc, 0.0);
                out[0] = (float)total;
                g_acc = 0.0;
                g_done = 0;
            }
        }
    }
}

// ---------------------------------------------------------------------------
extern "C" void kernel_launch(void* const* d_in, const int* in_sizes, int n_in,
                              void* d_out, int out_size) {
    const float* masked_dofs = (const float*)d_in[0];
    const float* full_dofs   = (const float*)d_in[1];
    const float* k_tor       = (const float*)d_in[2];
    const float* n_per       = (const float*)d_in[3];
    const float* delta       = (const float*)d_in[4];
    const int*   mask_idx    = (const int*)d_in[5];
    const int*   parent      = (const int*)d_in[6];
    const int*   tors        = (const int*)d_in[7];

    int K = in_sizes[0] / 9;
    int N = in_sizes[1] / 9;
    int M = in_sizes[2];

    int b0 = (N < L0B) ? N : L0B;
    int b1 = (N < L1B) ? N : L1B;
    int b2 = (N < L2B) ? N : L2B;
    int b3 = (N < L3B) ? N : L3B;

    const int TB = 256;
    k_local<<<(N + TB - 1) / TB, TB>>>(full_dofs, masked_dofs, mask_idx, parent,
                                       N, K);
    k_scatter<<<256, TB>>>(masked_dofs, mask_idx, parent, K);
    k_glob<<<(b0 + TB - 1) / TB, TB>>>(0, b0, 1);
    if (b1 > b0) k_glob<<<(b1 - b0 + TB - 1) / TB, TB>>>(b0, b1, b0);
    if (b2 > b1) k_glob<<<(b2 - b1 + TB - 1) / TB, TB>>>(b1, b2, b1);
    if (b3 > b2) k_glob<<<(b3 - b2 + TB - 1) / TB, TB>>>(b2, b3, b2);
    if (N > b3)  k_coords<<<(N - b3 + TB - 1) / TB, TB>>>(N);
    k_energy<<<(M + TB - 1) / TB, TB>>>(tors, k_tor, n_per, delta, M,
                                        (float*)d_out);
}